// round 6
// baseline (speedup 1.0000x reference)
#include <cuda_runtime.h>
#include <cuda_bf16.h>
#include <cuda_fp16.h>
#include <cstdint>
#include <math.h>

#define BB   128
#define SS   64
#define HH   128
#define WWID 256
#define DD   136
#define DIN  64
#define GM   (BB * SS)           // 8192
#define GN   (WWID * HH)         // 32768
#define KT   432                 // 3 x 144 interleaved passes
#define KC   48                  // K chunk
#define NCH  (KT / KC)           // 9
#define CL   4
#define RPC  4
#define NCLUS (BB / RPC)
#define SCAN_CTAS (NCLUS * CL)

// ---------------- device scratch ----------------
__device__ __half g_Gh[(size_t)GM * GN];        // 512 MB fp16
__device__ float g_cbias[GM * HH];
__device__ float g_h0[BB * HH];
__device__ __nv_bfloat16 g_A2[(size_t)GM * KT];  // 7.1 MB
__device__ __nv_bfloat16 g_B2[(size_t)GN * KT];  // 28.3 MB

// ---------------- helpers ----------------
__device__ __forceinline__ uint32_t s2u(const void* p) {
    uint32_t a;
    asm("{ .reg .u64 t; cvta.to.shared.u64 t, %1; cvt.u32.u64 %0, t; }" : "=r"(a) : "l"(p));
    return a;
}
__device__ __forceinline__ float2 fma2(float2 d, float2 a, float2 b) {
    union U { float2 f; unsigned long long u; };
    U ud, ua, ub; ud.f = d; ua.f = a; ub.f = b;
    asm("fma.rn.f32x2 %0, %1, %2, %0;" : "+l"(ud.u) : "l"(ua.u), "l"(ub.u));
    return ud.f;
}
__device__ __forceinline__ void st_cluster_f32(uint32_t addr, uint32_t rank, float v) {
    asm volatile("{\n\t.reg .b32 ra;\n\tmapa.shared::cluster.u32 ra, %0, %1;\n\t"
                 "st.shared::cluster.f32 [ra], %2;\n\t}"
                 :: "r"(addr), "r"(rank), "f"(v) : "memory");
}
__device__ __forceinline__ uint32_t cl_rank() {
    uint32_t r; asm("mov.u32 %0, %%cluster_ctarank;" : "=r"(r)); return r;
}
#define CL_SYNC() do { \
    asm volatile("barrier.cluster.arrive.aligned;" ::: "memory"); \
    asm volatile("barrier.cluster.wait.aligned;" ::: "memory"); } while (0)
template <int N> __device__ __forceinline__ void cp_wait() {
    asm volatile("cp.async.wait_group %0;" :: "n"(N));
}
__device__ __forceinline__ void cp_commit() {
    asm volatile("cp.async.commit_group;" ::: "memory");
}
__device__ __forceinline__ void cp16(uint32_t s, const void* g) {
    asm volatile("cp.async.cg.shared.global [%0], [%1], 16;" :: "r"(s), "l"(g));
}

// ---------------- h0 ----------------
__global__ void k_h0(const float* __restrict__ initial, const float* __restrict__ in_w,
                     const float* __restrict__ in_b, float* __restrict__ out, int write_feat) {
    int b = blockIdx.x, t = threadIdx.x;
    __shared__ float si[DIN];
    if (t < DIN) si[t] = initial[b * DIN + t];
    __syncthreads();
    float acc = in_b[t];
    #pragma unroll 8
    for (int k = 0; k < DIN; ++k) acc = fmaf(si[k], in_w[k * HH + t], acc);
    g_h0[b * HH + t] = acc;
    if (write_feat) out[(size_t)b * (SS + 1) * HH + t] = acc;
}

// ---------------- interleaved bf16 hi/lo splits ----------------
// pass layout along K: A = [hi | hi | lo], B = [hi | lo | hi]
__global__ void k_splitA(const float* __restrict__ logsig) {
    int i = blockIdx.x, c = threadIdx.x;   // 144 threads
    float v = (c < DD) ? logsig[(size_t)i * (DD + 1) + 1 + c] : 0.f;
    __nv_bfloat16 hi = __float2bfloat16(v);
    __nv_bfloat16 lo = __float2bfloat16(v - __bfloat162float(hi));
    size_t base = (size_t)i * KT + c;
    g_A2[base] = hi; g_A2[base + 144] = hi; g_A2[base + 288] = lo;
}
__global__ void k_splitB(const float* __restrict__ ml_w) {
    int j = blockIdx.x, c = threadIdx.x;   // j = w*128 + h
    int w = j >> 7, h = j & 127;
    float v = (c < DD) ? ml_w[(size_t)w * (HH * DD) + h * DD + c] : 0.f;
    __nv_bfloat16 hi = __float2bfloat16(v);
    __nv_bfloat16 lo = __float2bfloat16(v - __bfloat162float(hi));
    size_t base = (size_t)j * KT + c;
    g_B2[base] = hi; g_B2[base + 144] = lo; g_B2[base + 288] = hi;
}

// ---------------- cbias ----------------
__global__ void k_cbias(const float* __restrict__ logsig, const float* __restrict__ ml_b) {
    extern __shared__ float s[];
    float* mlb  = s;
    float* coef = s + HH * 137;
    float* part = coef + 160;
    int t = threadIdx.x;
    for (int idx = t; idx < HH * DD; idx += 256) {
        int h = idx / DD, d = idx - h * DD;
        mlb[h * 137 + d] = ml_b[idx];
    }
    int i0 = blockIdx.x * 16;
    for (int r = 0; r < 16; ++r) {
        int i = i0 + r;
        __syncthreads();
        if (t < DD) coef[t] = logsig[(size_t)i * (DD + 1) + 1 + t];
        __syncthreads();
        int h = t & 127, half = t >> 7;
        int d0 = half * 68;
        float acc = 0.f;
        #pragma unroll 4
        for (int d = 0; d < 68; ++d) acc = fmaf(coef[d0 + d], mlb[h * 137 + d0 + d], acc);
        part[t] = acc;
        __syncthreads();
        if (t < HH) g_cbias[(size_t)i * HH + t] = part[t] + part[t + 128];
    }
}

// ---------------- pipelined single-pass bf16 GEMM (K=432) -> fp16 G ----------------
#define SRK  56                       // smem row stride (halves); 112B, ldmatrix conflict-free
#define ABUF (128 * SRK)              // halves per operand buffer
#define SMEM_G2 (4 * ABUF * 2)        // 57344 B (A0,B0,A1,B1)
#define NT   ((GM / 128) * (GN / 128))  // 16384 tiles

__device__ __forceinline__ void ldm_x4(uint32_t* r, uint32_t addr) {
    asm volatile("ldmatrix.sync.aligned.m8n8.x4.shared.b16 {%0,%1,%2,%3}, [%4];"
                 : "=r"(r[0]), "=r"(r[1]), "=r"(r[2]), "=r"(r[3]) : "r"(addr));
}
__device__ __forceinline__ void mma_bf16(float* c, const uint32_t* a, const uint32_t* b) {
    asm volatile(
        "mma.sync.aligned.m16n8k16.row.col.f32.bf16.bf16.f32 "
        "{%0,%1,%2,%3}, {%4,%5,%6,%7}, {%8,%9}, {%0,%1,%2,%3};"
        : "+f"(c[0]), "+f"(c[1]), "+f"(c[2]), "+f"(c[3])
        : "r"(a[0]), "r"(a[1]), "r"(a[2]), "r"(a[3]), "r"(b[0]), "r"(b[1]));
}

// load one 128x48 A chunk + 128x48 B chunk via cp.async (1536 x 16B)
__device__ __forceinline__ void load_chunk(int i0, int j0, int ch,
                                           uint32_t smA, uint32_t smB, int t) {
    const __nv_bfloat16* Ab = g_A2 + (size_t)i0 * KT + ch * KC;
    const __nv_bfloat16* Bb = g_B2 + (size_t)j0 * KT + ch * KC;
    #pragma unroll
    for (int rep = 0; rep < 6; ++rep) {
        int id = rep * 256 + t;            // 0..1535
        int isB = (id >= 768);
        int lid = isB ? id - 768 : id;
        int row = lid / 6, c16 = lid - row * 6;
        const __nv_bfloat16* g = (isB ? Bb : Ab) + (size_t)row * KT + c16 * 8;
        uint32_t s = (isB ? smB : smA) + (uint32_t)(row * SRK + c16 * 8) * 2;
        cp16(s, g);
    }
}

__global__ void __launch_bounds__(256, 2) k_gemm_mma() {
    extern __shared__ __nv_bfloat16 sm[];
    uint32_t smBase = s2u(sm);
    uint32_t smA[2] = { smBase, smBase + 2u * ABUF * 2u };
    uint32_t smB[2] = { smBase + (uint32_t)ABUF * 2u, smBase + 3u * ABUF * 2u };

    int t = threadIdx.x, lane = t & 31;
    int wid = t >> 5, wm = wid >> 2, wn = wid & 3;

    int arow = (lane & 7) + ((lane >> 3) & 1) * 8;
    int acol = (lane >> 4) * 8;
    int brow = (lane & 7) + ((lane >> 4) & 1) * 8;
    int bcol = ((lane >> 3) & 1) * 8;
    uint32_t aoff[4], boff[2];
    #pragma unroll
    for (int mf = 0; mf < 4; ++mf)
        aoff[mf] = (uint32_t)((wm * 64 + mf * 16 + arow) * SRK + acol) * 2;
    #pragma unroll
    for (int nf = 0; nf < 2; ++nf)
        boff[nf] = (uint32_t)((wn * 32 + nf * 16 + brow) * SRK + bcol) * 2;

    int tile = blockIdx.x;
    int i0 = ((tile >> 8) << 7), j0 = ((tile & 255) << 7);
    if (tile < NT) { load_chunk(i0, j0, 0, smA[0], smB[0], t); cp_commit(); }

    for (; tile < NT; tile += gridDim.x) {
        float acc[4][4][4];
        #pragma unroll
        for (int i = 0; i < 4; ++i)
            #pragma unroll
            for (int j = 0; j < 4; ++j)
                #pragma unroll
                for (int q = 0; q < 4; ++q) acc[i][j][q] = 0.f;

        #pragma unroll 1
        for (int ch = 0; ch < NCH; ++ch) {
            if (ch < NCH - 1) {
                load_chunk(i0, j0, ch + 1, smA[(ch + 1) & 1], smB[(ch + 1) & 1], t);
                cp_commit();
                cp_wait<1>();
            } else {
                cp_wait<0>();
            }
            __syncthreads();
            uint32_t bA = smA[ch & 1], bB = smB[ch & 1];
            #pragma unroll
            for (int kg = 0; kg < 3; ++kg) {
                uint32_t koff = (uint32_t)kg * 32;   // 16 halves
                uint32_t aR[4][4], bR[4][2];
                #pragma unroll
                for (int mf = 0; mf < 4; ++mf) ldm_x4(aR[mf], bA + aoff[mf] + koff);
                #pragma unroll
                for (int nf = 0; nf < 2; ++nf) {
                    uint32_t r4[4];
                    ldm_x4(r4, bB + boff[nf] + koff);
                    bR[nf * 2][0] = r4[0]; bR[nf * 2][1] = r4[1];
                    bR[nf * 2 + 1][0] = r4[2]; bR[nf * 2 + 1][1] = r4[3];
                }
                #pragma unroll
                for (int mf = 0; mf < 4; ++mf)
                    #pragma unroll
                    for (int nf = 0; nf < 4; ++nf)
                        mma_bf16(acc[mf][nf], aR[mf], bR[nf]);
            }
            __syncthreads();
        }

        // prefetch next tile's chunk 0 while doing the epilogue
        int ntile = tile + gridDim.x;
        int ni0 = ((ntile >> 8) << 7), nj0 = ((ntile & 255) << 7);
        if (ntile < NT) { load_chunk(ni0, nj0, 0, smA[0], smB[0], t); cp_commit(); }

        int rbase = i0 + wm * 64 + (lane >> 2);
        int cbase = j0 + wn * 32 + (lane & 3) * 2;
        #pragma unroll
        for (int mf = 0; mf < 4; ++mf) {
            #pragma unroll
            for (int nf = 0; nf < 4; ++nf) {
                size_t r0 = (size_t)(rbase + mf * 16) * GN + cbase + nf * 8;
                size_t r1 = r0 + 8 * (size_t)GN;
                *(__half2*)&g_Gh[r0] = __floats2half2_rn(acc[mf][nf][0], acc[mf][nf][1]);
                *(__half2*)&g_Gh[r1] = __floats2half2_rn(acc[mf][nf][2], acc[mf][nf][3]);
            }
        }
        i0 = ni0; j0 = nj0;
    }
}

// ---------------- cluster-4 scan (unchanged from R4) ----------------
#define OFF_W1  0
#define OFF_W2  8192
#define OFF_WV  24576
#define OFF_B1  40960
#define OFF_B2  41024
#define OFF_BV  41088
#define OFF_SY  41152
#define OFF_SYM 41664
#define OFF_SK1 42176
#define OFF_SK2 42688
#define OFF_A   43200
#define OFF_B2F 44224
#define OFF_RED 45248
#define SCAN_FLOATS 47296
#define SCAN_SMEM (SCAN_FLOATS * 4)

template <int K, int ACT>
__device__ __forceinline__ void mlp_stage(const float* __restrict__ sIn,
                                          const float* __restrict__ W,
                                          const float* __restrict__ bias,
                                          float* sRed, uint32_t outAddr,
                                          int r, int t) {
    const int Kc = K / 4;
    int kc = t >> 6, n = t & 63;
    float2 a01 = make_float2(0.f, 0.f), a23 = make_float2(0.f, 0.f);
    const float* Wp = W + n;
    #pragma unroll 8
    for (int kk = 0; kk < Kc; ++kk) {
        int k = kc * Kc + kk;
        float w = Wp[k * 64];
        float4 a = *(const float4*)&sIn[k * 4];
        float2 w2 = make_float2(w, w);
        a01 = fma2(a01, make_float2(a.x, a.y), w2);
        a23 = fma2(a23, make_float2(a.z, a.w), w2);
    }
    *(float4*)&sRed[t * 4] = make_float4(a01.x, a01.y, a23.x, a23.y);
    __syncthreads();
    {
        int n2 = t & 63, j = t >> 6;
        float v = sRed[(0 * 64 + n2) * 4 + j] + sRed[(1 * 64 + n2) * 4 + j]
                + sRed[(2 * 64 + n2) * 4 + j] + sRed[(3 * 64 + n2) * 4 + j];
        v += bias[n2];
        if (ACT == 0) v = fmaxf(v, 0.f); else v = tanhf(v);
        uint32_t addr = outAddr + (uint32_t)(((64 * r + n2) << 2) + j) * 4u;
        #pragma unroll
        for (int p = 0; p < CL; ++p) st_cluster_f32(addr, (uint32_t)p, v);
    }
    CL_SYNC();
}

__device__ __forceinline__ void contract_stage(const float* __restrict__ sV,
                                               int m, int b0, int r,
                                               float* sRed, uint32_t kAddr,
                                               const float* __restrict__ cbias,
                                               int t) {
    int wg = t >> 4, hp = t & 15;
    float cb = 0.f;
    if (t < 128) {
        int j = t & 3, hh = t >> 2;
        cb = cbias[((size_t)(b0 + j) * SS + m) * HH + 32 * r + hh];
    }
    const __half2* Gp[RPC];
    #pragma unroll
    for (int j = 0; j < RPC; ++j)
        Gp[j] = (const __half2*)(g_Gh + ((size_t)(b0 + j) * SS + m) * GN) + 16 * r + hp;
    float2 acc[RPC];
    #pragma unroll
    for (int j = 0; j < RPC; ++j) acc[j] = make_float2(0.f, 0.f);
    #pragma unroll 4
    for (int ww = 0; ww < 16; ++ww) {
        int w = wg * 16 + ww;
        float4 v4 = *(const float4*)&sV[w * 4];
        const float* vp = (const float*)&v4;
        #pragma unroll
        for (int j = 0; j < RPC; ++j) {
            float2 g = __half22float2(Gp[j][(size_t)w * 64]);
            acc[j] = fma2(acc[j], make_float2(vp[j], vp[j]), g);
        }
    }
    #pragma unroll
    for (int j = 0; j < RPC; ++j) {
        sRed[wg * 128 + (2 * hp) * 4 + j]     = acc[j].x;
        sRed[wg * 128 + (2 * hp + 1) * 4 + j] = acc[j].y;
    }
    __syncthreads();
    if (t < 128) {
        int j = t & 3, hh = t >> 2;
        float v = cb;
        #pragma unroll
        for (int q = 0; q < 16; ++q) v += sRed[q * 128 + hh * 4 + j];
        uint32_t addr = kAddr + (uint32_t)(((32 * r + hh) << 2) + j) * 4u;
        #pragma unroll
        for (int p = 0; p < CL; ++p) st_cluster_f32(addr, (uint32_t)p, v);
    }
    CL_SYNC();
}

__global__ void __launch_bounds__(256, 1) __cluster_dims__(CL, 1, 1)
k_scan(const float* __restrict__ h1_w, const float* __restrict__ h1_b,
       const float* __restrict__ h2_w, const float* __restrict__ h2_b,
       const float* __restrict__ vo_w, const float* __restrict__ vo_b,
       float* __restrict__ out, int write_feat, long long last_off) {
    extern __shared__ float ss[];
    float* w1s = ss + OFF_W1;
    float* w2s = ss + OFF_W2;
    float* wvs = ss + OFF_WV;
    float* b1s = ss + OFF_B1;
    float* b2s = ss + OFF_B2;
    float* bvs = ss + OFF_BV;
    float* sy  = ss + OFF_SY;
    float* sym = ss + OFF_SYM;
    float* sk1 = ss + OFF_SK1;
    float* sk2 = ss + OFF_SK2;
    float* sbA = ss + OFF_A;
    float* sbB = ss + OFF_B2F;
    float* sRed = ss + OFF_RED;

    int t = threadIdx.x;
    int r = (int)cl_rank();
    int b0 = (blockIdx.x >> 2) * RPC;

    uint32_t aA  = s2u(sbA), aB = s2u(sbB);
    uint32_t aK1 = s2u(sk1), aK2 = s2u(sk2);

    for (int idx = t; idx < HH * 64; idx += 256) {
        int k = idx >> 6, n = idx & 63;
        w1s[idx] = h1_w[k * WWID + 64 * r + n];
    }
    for (int idx = t; idx < WWID * 64; idx += 256) {
        int k = idx >> 6, n = idx & 63;
        w2s[idx] = h2_w[k * WWID + 64 * r + n];
        wvs[idx] = vo_w[k * WWID + 64 * r + n];
    }
    if (t < 64) {
        b1s[t] = h1_b[64 * r + t];
        b2s[t] = h2_b[64 * r + t];
        bvs[t] = vo_b[64 * r + t];
    }
    for (int idx = t; idx < HH * RPC; idx += 256) {
        int h = idx >> 2, j = idx & 3;
        sy[idx] = g_h0[(b0 + j) * HH + h];
    }
    __syncthreads();

    for (int n = 0; n < SS; ++n) {
        int m1 = (n > 0) ? (n - 1) : 0;
        mlp_stage<HH, 0>(sy, w1s, b1s, sRed, aA, r, t);
        mlp_stage<WWID, 0>(sbA, w2s, b2s, sRed, aB, r, t);
        mlp_stage<WWID, 1>(sbB, wvs, bvs, sRed, aA, r, t);
        contract_stage(sbA, m1, b0, r, sRed, aK1, g_cbias, t);
        {
            int i0 = t, i1 = t + 256;
            sym[i0] = sy[i0] + sk1[i0];
            sym[i1] = sy[i1] + sk1[i1];
        }
        __syncthreads();
        mlp_stage<HH, 0>(sym, w1s, b1s, sRed, aA, r, t);
        mlp_stage<WWID, 0>(sbA, w2s, b2s, sRed, aB, r, t);
        mlp_stage<WWID, 1>(sbB, wvs, bvs, sRed, aA, r, t);
        contract_stage(sbA, n, b0, r, sRed, aK2, g_cbias, t);
        {
            #pragma unroll
            for (int u = 0; u < 2; ++u) {
                int v = t + u * 256;
                int h = v >> 2, j = v & 3;
                float yn = sy[v] + 0.5f * (sk1[v] + sk2[v]);
                sy[v] = yn;
                if (write_feat)
                    out[(size_t)(b0 + j) * (SS + 1) * HH + (size_t)(n + 1) * HH + h] = yn;
                if (n == SS - 1 && last_off >= 0)
                    out[(size_t)last_off + (size_t)(b0 + j) * HH + h] = yn;
            }
        }
        __syncthreads();
    }
}

// ---------------- launch ----------------
extern "C" void kernel_launch(void* const* d_in, const int* in_sizes, int n_in,
                              void* d_out, int out_size) {
    const float* logsig  = (const float*)d_in[1];
    const float* initial = (const float*)d_in[2];
    const float* in_w    = (const float*)d_in[3];
    const float* in_b    = (const float*)d_in[4];
    const float* h1_w    = (const float*)d_in[5];
    const float* h1_b    = (const float*)d_in[6];
    const float* h2_w    = (const float*)d_in[7];
    const float* h2_b    = (const float*)d_in[8];
    const float* vo_w    = (const float*)d_in[9];
    const float* vo_b    = (const float*)d_in[10];
    const float* ml_w    = (const float*)d_in[11];
    const float* ml_b    = (const float*)d_in[12];
    float* out = (float*)d_out;

    const long long feat_sz = (long long)BB * (SS + 1) * HH;
    const long long last_sz = (long long)BB * HH;
    int write_feat = (out_size >= feat_sz) ? 1 : 0;
    long long last_off = -1;
    if (out_size >= feat_sz + last_sz) last_off = feat_sz;
    else if (!write_feat && out_size >= last_sz) last_off = 0;

    const int cbias_smem = (HH * 137 + 160 + 256) * 4;
    cudaFuncSetAttribute(k_cbias,    cudaFuncAttributeMaxDynamicSharedMemorySize, cbias_smem);
    cudaFuncSetAttribute(k_gemm_mma, cudaFuncAttributeMaxDynamicSharedMemorySize, SMEM_G2);
    cudaFuncSetAttribute(k_scan,     cudaFuncAttributeMaxDynamicSharedMemorySize, SCAN_SMEM);

    k_h0<<<BB, HH>>>(initial, in_w, in_b, out, write_feat);
    k_splitA<<<GM, 144>>>(logsig);
    k_splitB<<<GN, 144>>>(ml_w);
    k_cbias<<<GM / 16, 256, cbias_smem>>>(logsig, ml_b);
    k_gemm_mma<<<296, 256, SMEM_G2>>>();
    k_scan<<<SCAN_CTAS, 256, SCAN_SMEM>>>(h1_w, h1_b, h2_w, h2_b, vo_w, vo_b,
                                          out, write_feat, last_off);
}

// round 7
// speedup vs baseline: 1.3322x; 1.3322x over previous
#include <cuda_runtime.h>
#include <cuda_fp16.h>
#include <cstdint>
#include <math.h>

#define BB   128
#define SS   64
#define HH   128
#define WWID 256
#define DD   136
#define DIN  64
#define GM   (BB * SS)           // 8192
#define GN   (WWID * HH)         // 32768
#define KT   144                 // single-pass fp16, K padded 136 -> 144
#define KC   48
#define NCH  (KT / KC)           // 3
#define CL   4
#define RPC  4
#define NCLUS (BB / RPC)
#define SCAN_CTAS (NCLUS * CL)

// ---------------- device scratch ----------------
__device__ __half g_Gh[(size_t)GM * GN];        // 512 MB fp16
__device__ float g_cbias[GM * HH];
__device__ float g_h0[BB * HH];
__device__ __half g_A2[(size_t)GM * KT];        // 2.4 MB
__device__ __half g_B2[(size_t)GN * KT];        // 9.4 MB

// ---------------- helpers ----------------
__device__ __forceinline__ uint32_t s2u(const void* p) {
    uint32_t a;
    asm("{ .reg .u64 t; cvta.to.shared.u64 t, %1; cvt.u32.u64 %0, t; }" : "=r"(a) : "l"(p));
    return a;
}
__device__ __forceinline__ float2 fma2(float2 d, float2 a, float2 b) {
    union U { float2 f; unsigned long long u; };
    U ud, ua, ub; ud.f = d; ua.f = a; ub.f = b;
    asm("fma.rn.f32x2 %0, %1, %2, %0;" : "+l"(ud.u) : "l"(ua.u), "l"(ub.u));
    return ud.f;
}
__device__ __forceinline__ void st_cluster_f32(uint32_t addr, uint32_t rank, float v) {
    asm volatile("{\n\t.reg .b32 ra;\n\tmapa.shared::cluster.u32 ra, %0, %1;\n\t"
                 "st.shared::cluster.f32 [ra], %2;\n\t}"
                 :: "r"(addr), "r"(rank), "f"(v) : "memory");
}
__device__ __forceinline__ uint32_t cl_rank() {
    uint32_t r; asm("mov.u32 %0, %%cluster_ctarank;" : "=r"(r)); return r;
}
#define CL_SYNC() do { \
    asm volatile("barrier.cluster.arrive.aligned;" ::: "memory"); \
    asm volatile("barrier.cluster.wait.aligned;" ::: "memory"); } while (0)
template <int N> __device__ __forceinline__ void cp_wait() {
    asm volatile("cp.async.wait_group %0;" :: "n"(N));
}
__device__ __forceinline__ void cp_commit() {
    asm volatile("cp.async.commit_group;" ::: "memory");
}
__device__ __forceinline__ void cp16(uint32_t s, const void* g) {
    asm volatile("cp.async.cg.shared.global [%0], [%1], 16;" :: "r"(s), "l"(g));
}

// ---------------- h0 ----------------
__global__ void k_h0(const float* __restrict__ initial, const float* __restrict__ in_w,
                     const float* __restrict__ in_b, float* __restrict__ out, int write_feat) {
    int b = blockIdx.x, t = threadIdx.x;
    __shared__ float si[DIN];
    if (t < DIN) si[t] = initial[b * DIN + t];
    __syncthreads();
    float acc = in_b[t];
    #pragma unroll 8
    for (int k = 0; k < DIN; ++k) acc = fmaf(si[k], in_w[k * HH + t], acc);
    g_h0[b * HH + t] = acc;
    if (write_feat) out[(size_t)b * (SS + 1) * HH + t] = acc;
}

// ---------------- fp16 operand conversion (K padded to 144 with zeros) ----------------
__global__ void k_splitA(const float* __restrict__ logsig) {
    int i = blockIdx.x, c = threadIdx.x;   // 144 threads
    float v = (c < DD) ? logsig[(size_t)i * (DD + 1) + 1 + c] : 0.f;
    g_A2[(size_t)i * KT + c] = __float2half_rn(v);
}
__global__ void k_splitB(const float* __restrict__ ml_w) {
    int j = blockIdx.x, c = threadIdx.x;   // j = w*128 + h
    int w = j >> 7, h = j & 127;
    float v = (c < DD) ? ml_w[(size_t)w * (HH * DD) + h * DD + c] : 0.f;
    g_B2[(size_t)j * KT + c] = __float2half_rn(v);
}

// ---------------- cbias ----------------
__global__ void k_cbias(const float* __restrict__ logsig, const float* __restrict__ ml_b) {
    extern __shared__ float s[];
    float* mlb  = s;
    float* coef = s + HH * 137;
    float* part = coef + 160;
    int t = threadIdx.x;
    for (int idx = t; idx < HH * DD; idx += 256) {
        int h = idx / DD, d = idx - h * DD;
        mlb[h * 137 + d] = ml_b[idx];
    }
    int i0 = blockIdx.x * 16;
    for (int r = 0; r < 16; ++r) {
        int i = i0 + r;
        __syncthreads();
        if (t < DD) coef[t] = logsig[(size_t)i * (DD + 1) + 1 + t];
        __syncthreads();
        int h = t & 127, half = t >> 7;
        int d0 = half * 68;
        float acc = 0.f;
        #pragma unroll 4
        for (int d = 0; d < 68; ++d) acc = fmaf(coef[d0 + d], mlb[h * 137 + d0 + d], acc);
        part[t] = acc;
        __syncthreads();
        if (t < HH) g_cbias[(size_t)i * HH + t] = part[t] + part[t + 128];
    }
}

// ---------------- single-pass fp16 GEMM (K=144) -> fp16 G ----------------
#define SRK  56                       // smem row stride (halves)
#define ABUF (128 * SRK)
#define SMEM_G2 (4 * ABUF * 2)        // 57344 B

__device__ __forceinline__ void ldm_x4(uint32_t* r, uint32_t addr) {
    asm volatile("ldmatrix.sync.aligned.m8n8.x4.shared.b16 {%0,%1,%2,%3}, [%4];"
                 : "=r"(r[0]), "=r"(r[1]), "=r"(r[2]), "=r"(r[3]) : "r"(addr));
}
__device__ __forceinline__ void mma_f16(float* c, const uint32_t* a, const uint32_t* b) {
    asm volatile(
        "mma.sync.aligned.m16n8k16.row.col.f32.f16.f16.f32 "
        "{%0,%1,%2,%3}, {%4,%5,%6,%7}, {%8,%9}, {%0,%1,%2,%3};"
        : "+f"(c[0]), "+f"(c[1]), "+f"(c[2]), "+f"(c[3])
        : "r"(a[0]), "r"(a[1]), "r"(a[2]), "r"(a[3]), "r"(b[0]), "r"(b[1]));
}

// load one 128x48 A chunk + 128x48 B chunk via cp.async (1536 x 16B)
__device__ __forceinline__ void load_chunk(int i0, int j0, int ch,
                                           uint32_t smA, uint32_t smB, int t) {
    const __half* Ab = g_A2 + (size_t)i0 * KT + ch * KC;
    const __half* Bb = g_B2 + (size_t)j0 * KT + ch * KC;
    #pragma unroll
    for (int rep = 0; rep < 6; ++rep) {
        int id = rep * 256 + t;
        int isB = (id >= 768);
        int lid = isB ? id - 768 : id;
        int row = lid / 6, c16 = lid - row * 6;
        const __half* g = (isB ? Bb : Ab) + (size_t)row * KT + c16 * 8;
        uint32_t s = (isB ? smB : smA) + (uint32_t)(row * SRK + c16 * 8) * 2;
        cp16(s, g);
    }
}

__global__ void __launch_bounds__(256, 1) k_gemm_mma() {
    extern __shared__ __half sm[];
    uint32_t smBase = s2u(sm);
    uint32_t smA[2] = { smBase, smBase + 2u * ABUF * 2u };
    uint32_t smB[2] = { smBase + (uint32_t)ABUF * 2u, smBase + 3u * ABUF * 2u };

    int t = threadIdx.x, lane = t & 31;
    int wid = t >> 5, wm = wid >> 2, wn = wid & 3;
    int j0 = blockIdx.x << 7, i0 = blockIdx.y << 7;

    int arow = (lane & 7) + ((lane >> 3) & 1) * 8;
    int acol = (lane >> 4) * 8;
    int brow = (lane & 7) + ((lane >> 4) & 1) * 8;
    int bcol = ((lane >> 3) & 1) * 8;
    uint32_t aoff[4], boff[2];
    #pragma unroll
    for (int mf = 0; mf < 4; ++mf)
        aoff[mf] = (uint32_t)((wm * 64 + mf * 16 + arow) * SRK + acol) * 2;
    #pragma unroll
    for (int nf = 0; nf < 2; ++nf)
        boff[nf] = (uint32_t)((wn * 32 + nf * 16 + brow) * SRK + bcol) * 2;

    // prologue: prefetch chunks 0 and 1
    load_chunk(i0, j0, 0, smA[0], smB[0], t); cp_commit();
    load_chunk(i0, j0, 1, smA[1], smB[1], t); cp_commit();

    float acc[4][4][4];
    #pragma unroll
    for (int i = 0; i < 4; ++i)
        #pragma unroll
        for (int j = 0; j < 4; ++j)
            #pragma unroll
            for (int q = 0; q < 4; ++q) acc[i][j][q] = 0.f;

    #pragma unroll
    for (int ch = 0; ch < NCH; ++ch) {
        if (ch == 0) cp_wait<1>();
        else if (ch == 1) cp_wait<1>();
        else cp_wait<0>();
        __syncthreads();
        uint32_t bA = smA[ch % 2], bB = smB[ch % 2];
        #pragma unroll
        for (int kg = 0; kg < 3; ++kg) {
            uint32_t koff = (uint32_t)kg * 32;
            uint32_t aR[4][4], bR[4][2];
            #pragma unroll
            for (int mf = 0; mf < 4; ++mf) ldm_x4(aR[mf], bA + aoff[mf] + koff);
            #pragma unroll
            for (int nf = 0; nf < 2; ++nf) {
                uint32_t r4[4];
                ldm_x4(r4, bB + boff[nf] + koff);
                bR[nf * 2][0] = r4[0]; bR[nf * 2][1] = r4[1];
                bR[nf * 2 + 1][0] = r4[2]; bR[nf * 2 + 1][1] = r4[3];
            }
            #pragma unroll
            for (int mf = 0; mf < 4; ++mf)
                #pragma unroll
                for (int nf = 0; nf < 4; ++nf)
                    mma_f16(acc[mf][nf], aR[mf], bR[nf]);
        }
        if (ch == 0) {   // kick off chunk 2 into buffer 0 after it's consumed
            __syncthreads();
            load_chunk(i0, j0, 2, smA[0], smB[0], t);
            cp_commit();
        }
    }

    int rbase = i0 + wm * 64 + (lane >> 2);
    int cbase = j0 + wn * 32 + (lane & 3) * 2;
    #pragma unroll
    for (int mf = 0; mf < 4; ++mf) {
        #pragma unroll
        for (int nf = 0; nf < 4; ++nf) {
            size_t r0 = (size_t)(rbase + mf * 16) * GN + cbase + nf * 8;
            size_t r1 = r0 + 8 * (size_t)GN;
            *(__half2*)&g_Gh[r0] = __floats2half2_rn(acc[mf][nf][0], acc[mf][nf][1]);
            *(__half2*)&g_Gh[r1] = __floats2half2_rn(acc[mf][nf][2], acc[mf][nf][3]);
        }
    }
}

// ---------------- cluster-4 scan (unchanged from R4) ----------------
#define OFF_W1  0
#define OFF_W2  8192
#define OFF_WV  24576
#define OFF_B1  40960
#define OFF_B2  41024
#define OFF_BV  41088
#define OFF_SY  41152
#define OFF_SYM 41664
#define OFF_SK1 42176
#define OFF_SK2 42688
#define OFF_A   43200
#define OFF_B2F 44224
#define OFF_RED 45248
#define SCAN_FLOATS 47296
#define SCAN_SMEM (SCAN_FLOATS * 4)

template <int K, int ACT>
__device__ __forceinline__ void mlp_stage(const float* __restrict__ sIn,
                                          const float* __restrict__ W,
                                          const float* __restrict__ bias,
                                          float* sRed, uint32_t outAddr,
                                          int r, int t) {
    const int Kc = K / 4;
    int kc = t >> 6, n = t & 63;
    float2 a01 = make_float2(0.f, 0.f), a23 = make_float2(0.f, 0.f);
    const float* Wp = W + n;
    #pragma unroll 8
    for (int kk = 0; kk < Kc; ++kk) {
        int k = kc * Kc + kk;
        float w = Wp[k * 64];
        float4 a = *(const float4*)&sIn[k * 4];
        float2 w2 = make_float2(w, w);
        a01 = fma2(a01, make_float2(a.x, a.y), w2);
        a23 = fma2(a23, make_float2(a.z, a.w), w2);
    }
    *(float4*)&sRed[t * 4] = make_float4(a01.x, a01.y, a23.x, a23.y);
    __syncthreads();
    {
        int n2 = t & 63, j = t >> 6;
        float v = sRed[(0 * 64 + n2) * 4 + j] + sRed[(1 * 64 + n2) * 4 + j]
                + sRed[(2 * 64 + n2) * 4 + j] + sRed[(3 * 64 + n2) * 4 + j];
        v += bias[n2];
        if (ACT == 0) v = fmaxf(v, 0.f); else v = tanhf(v);
        uint32_t addr = outAddr + (uint32_t)(((64 * r + n2) << 2) + j) * 4u;
        #pragma unroll
        for (int p = 0; p < CL; ++p) st_cluster_f32(addr, (uint32_t)p, v);
    }
    CL_SYNC();
}

__device__ __forceinline__ void contract_stage(const float* __restrict__ sV,
                                               int m, int b0, int r,
                                               float* sRed, uint32_t kAddr,
                                               const float* __restrict__ cbias,
                                               int t) {
    int wg = t >> 4, hp = t & 15;
    float cb = 0.f;
    if (t < 128) {
        int j = t & 3, hh = t >> 2;
        cb = cbias[((size_t)(b0 + j) * SS + m) * HH + 32 * r + hh];
    }
    const __half2* Gp[RPC];
    #pragma unroll
    for (int j = 0; j < RPC; ++j)
        Gp[j] = (const __half2*)(g_Gh + ((size_t)(b0 + j) * SS + m) * GN) + 16 * r + hp;
    float2 acc[RPC];
    #pragma unroll
    for (int j = 0; j < RPC; ++j) acc[j] = make_float2(0.f, 0.f);
    #pragma unroll 4
    for (int ww = 0; ww < 16; ++ww) {
        int w = wg * 16 + ww;
        float4 v4 = *(const float4*)&sV[w * 4];
        const float* vp = (const float*)&v4;
        #pragma unroll
        for (int j = 0; j < RPC; ++j) {
            float2 g = __half22float2(Gp[j][(size_t)w * 64]);
            acc[j] = fma2(acc[j], make_float2(vp[j], vp[j]), g);
        }
    }
    #pragma unroll
    for (int j = 0; j < RPC; ++j) {
        sRed[wg * 128 + (2 * hp) * 4 + j]     = acc[j].x;
        sRed[wg * 128 + (2 * hp + 1) * 4 + j] = acc[j].y;
    }
    __syncthreads();
    if (t < 128) {
        int j = t & 3, hh = t >> 2;
        float v = cb;
        #pragma unroll
        for (int q = 0; q < 16; ++q) v += sRed[q * 128 + hh * 4 + j];
        uint32_t addr = kAddr + (uint32_t)(((32 * r + hh) << 2) + j) * 4u;
        #pragma unroll
        for (int p = 0; p < CL; ++p) st_cluster_f32(addr, (uint32_t)p, v);
    }
    CL_SYNC();
}

__global__ void __launch_bounds__(256, 1) __cluster_dims__(CL, 1, 1)
k_scan(const float* __restrict__ h1_w, const float* __restrict__ h1_b,
       const float* __restrict__ h2_w, const float* __restrict__ h2_b,
       const float* __restrict__ vo_w, const float* __restrict__ vo_b,
       float* __restrict__ out, int write_feat, long long last_off) {
    extern __shared__ float ss[];
    float* w1s = ss + OFF_W1;
    float* w2s = ss + OFF_W2;
    float* wvs = ss + OFF_WV;
    float* b1s = ss + OFF_B1;
    float* b2s = ss + OFF_B2;
    float* bvs = ss + OFF_BV;
    float* sy  = ss + OFF_SY;
    float* sym = ss + OFF_SYM;
    float* sk1 = ss + OFF_SK1;
    float* sk2 = ss + OFF_SK2;
    float* sbA = ss + OFF_A;
    float* sbB = ss + OFF_B2F;
    float* sRed = ss + OFF_RED;

    int t = threadIdx.x;
    int r = (int)cl_rank();
    int b0 = (blockIdx.x >> 2) * RPC;

    uint32_t aA  = s2u(sbA), aB = s2u(sbB);
    uint32_t aK1 = s2u(sk1), aK2 = s2u(sk2);

    for (int idx = t; idx < HH * 64; idx += 256) {
        int k = idx >> 6, n = idx & 63;
        w1s[idx] = h1_w[k * WWID + 64 * r + n];
    }
    for (int idx = t; idx < WWID * 64; idx += 256) {
        int k = idx >> 6, n = idx & 63;
        w2s[idx] = h2_w[k * WWID + 64 * r + n];
        wvs[idx] = vo_w[k * WWID + 64 * r + n];
    }
    if (t < 64) {
        b1s[t] = h1_b[64 * r + t];
        b2s[t] = h2_b[64 * r + t];
        bvs[t] = vo_b[64 * r + t];
    }
    for (int idx = t; idx < HH * RPC; idx += 256) {
        int h = idx >> 2, j = idx & 3;
        sy[idx] = g_h0[(b0 + j) * HH + h];
    }
    __syncthreads();

    for (int n = 0; n < SS; ++n) {
        int m1 = (n > 0) ? (n - 1) : 0;
        mlp_stage<HH, 0>(sy, w1s, b1s, sRed, aA, r, t);
        mlp_stage<WWID, 0>(sbA, w2s, b2s, sRed, aB, r, t);
        mlp_stage<WWID, 1>(sbB, wvs, bvs, sRed, aA, r, t);
        contract_stage(sbA, m1, b0, r, sRed, aK1, g_cbias, t);
        {
            int i0 = t, i1 = t + 256;
            sym[i0] = sy[i0] + sk1[i0];
            sym[i1] = sy[i1] + sk1[i1];
        }
        __syncthreads();
        mlp_stage<HH, 0>(sym, w1s, b1s, sRed, aA, r, t);
        mlp_stage<WWID, 0>(sbA, w2s, b2s, sRed, aB, r, t);
        mlp_stage<WWID, 1>(sbB, wvs, bvs, sRed, aA, r, t);
        contract_stage(sbA, n, b0, r, sRed, aK2, g_cbias, t);
        {
            #pragma unroll
            for (int u = 0; u < 2; ++u) {
                int v = t + u * 256;
                int h = v >> 2, j = v & 3;
                float yn = sy[v] + 0.5f * (sk1[v] + sk2[v]);
                sy[v] = yn;
                if (write_feat)
                    out[(size_t)(b0 + j) * (SS + 1) * HH + (size_t)(n + 1) * HH + h] = yn;
                if (n == SS - 1 && last_off >= 0)
                    out[(size_t)last_off + (size_t)(b0 + j) * HH + h] = yn;
            }
        }
        __syncthreads();
    }
}

// ---------------- launch ----------------
extern "C" void kernel_launch(void* const* d_in, const int* in_sizes, int n_in,
                              void* d_out, int out_size) {
    const float* logsig  = (const float*)d_in[1];
    const float* initial = (const float*)d_in[2];
    const float* in_w    = (const float*)d_in[3];
    const float* in_b    = (const float*)d_in[4];
    const float* h1_w    = (const float*)d_in[5];
    const float* h1_b    = (const float*)d_in[6];
    const float* h2_w    = (const float*)d_in[7];
    const float* h2_b    = (const float*)d_in[8];
    const float* vo_w    = (const float*)d_in[9];
    const float* vo_b    = (const float*)d_in[10];
    const float* ml_w    = (const float*)d_in[11];
    const float* ml_b    = (const float*)d_in[12];
    float* out = (float*)d_out;

    const long long feat_sz = (long long)BB * (SS + 1) * HH;
    const long long last_sz = (long long)BB * HH;
    int write_feat = (out_size >= feat_sz) ? 1 : 0;
    long long last_off = -1;
    if (out_size >= feat_sz + last_sz) last_off = feat_sz;
    else if (!write_feat && out_size >= last_sz) last_off = 0;

    const int cbias_smem = (HH * 137 + 160 + 256) * 4;
    cudaFuncSetAttribute(k_cbias,    cudaFuncAttributeMaxDynamicSharedMemorySize, cbias_smem);
    cudaFuncSetAttribute(k_gemm_mma, cudaFuncAttributeMaxDynamicSharedMemorySize, SMEM_G2);
    cudaFuncSetAttribute(k_scan,     cudaFuncAttributeMaxDynamicSharedMemorySize, SCAN_SMEM);

    // gemm moved to launch slot 4 so the ncu capture window lands on it
    k_h0<<<BB, HH>>>(initial, in_w, in_b, out, write_feat);
    k_splitA<<<GM, KT>>>(logsig);
    k_splitB<<<GN, KT>>>(ml_w);
    k_gemm_mma<<<dim3(GN / 128, GM / 128), 256, SMEM_G2>>>();
    k_cbias<<<GM / 16, 256, cbias_smem>>>(logsig, ml_b);
    k_scan<<<SCAN_CTAS, 256, SCAN_SMEM>>>(h1_w, h1_b, h2_w, h2_b, vo_w, vo_b,
                                          out, write_feat, last_off);
}

// round 9
// speedup vs baseline: 1.4798x; 1.1107x over previous
#include <cuda_runtime.h>
#include <cuda_fp16.h>
#include <cstdint>
#include <math.h>

#define BB   128
#define SS   64
#define HH   128
#define WWID 256
#define DD   136
#define DIN  64
#define GM   (BB * SS)           // 8192
#define GN   (WWID * HH)         // 32768
#define KT   144                 // single-pass fp16, K padded 136 -> 144
#define KC   48
#define NCH  (KT / KC)           // 3
#define CL   4
#define RPC  4
#define NCLUS (BB / RPC)
#define SCAN_CTAS (NCLUS * CL)

// ---------------- device scratch ----------------
__device__ __half g_Gh[(size_t)GM * GN];        // 512 MB fp16
__device__ float g_cbias[GM * HH];
__device__ float g_h0[BB * HH];
__device__ __half g_A2[(size_t)GM * KT];        // 2.4 MB
__device__ __half g_B2[(size_t)GN * KT];        // 9.4 MB

// ---------------- helpers ----------------
__device__ __forceinline__ uint32_t s2u(const void* p) {
    uint32_t a;
    asm("{ .reg .u64 t; cvta.to.shared.u64 t, %1; cvt.u32.u64 %0, t; }" : "=r"(a) : "l"(p));
    return a;
}
__device__ __forceinline__ float2 fma2(float2 d, float2 a, float2 b) {
    union U { float2 f; unsigned long long u; };
    U ud, ua, ub; ud.f = d; ua.f = a; ub.f = b;
    asm("fma.rn.f32x2 %0, %1, %2, %0;" : "+l"(ud.u) : "l"(ua.u), "l"(ub.u));
    return ud.f;
}
__device__ __forceinline__ void st_cluster_f32(uint32_t addr, uint32_t rank, float v) {
    asm volatile("{\n\t.reg .b32 ra;\n\tmapa.shared::cluster.u32 ra, %0, %1;\n\t"
                 "st.shared::cluster.f32 [ra], %2;\n\t}"
                 :: "r"(addr), "r"(rank), "f"(v) : "memory");
}
__device__ __forceinline__ uint32_t cl_rank() {
    uint32_t r; asm("mov.u32 %0, %%cluster_ctarank;" : "=r"(r)); return r;
}
#define CL_SYNC() do { \
    asm volatile("barrier.cluster.arrive.aligned;" ::: "memory"); \
    asm volatile("barrier.cluster.wait.aligned;" ::: "memory"); } while (0)
#define MBAR_INIT(a, c) \
    asm volatile("mbarrier.init.shared.b64 [%0], %1;" :: "r"(a), "r"((uint32_t)(c)) : "memory")
template <int N> __device__ __forceinline__ void cp_wait() {
    asm volatile("cp.async.wait_group %0;" :: "n"(N));
}
__device__ __forceinline__ void cp_commit() {
    asm volatile("cp.async.commit_group;" ::: "memory");
}
__device__ __forceinline__ void cp16(uint32_t s, const void* g) {
    asm volatile("cp.async.cg.shared.global [%0], [%1], 16;" :: "r"(s), "l"(g));
}

// cluster-wide stage barrier: local sync, 4 remote release-arrives, acquire-wait
__device__ __forceinline__ void stage_bar(uint32_t mb, int& ph, int t) {
    __syncthreads();
    if (t < CL) {
        asm volatile("{\n\t.reg .b32 ra;\n\tmapa.shared::cluster.u32 ra, %0, %1;\n\t"
                     "mbarrier.arrive.release.cluster.shared::cluster.b64 _, [ra];\n\t}"
                     :: "r"(mb), "r"((uint32_t)t) : "memory");
    }
    uint32_t par = (uint32_t)(ph & 1), done;
    asm volatile("{\n\t.reg .pred p;\n\t"
        "mbarrier.try_wait.parity.acquire.cluster.shared::cta.b64 p, [%1], %2;\n\t"
        "selp.b32 %0, 1, 0, p;\n\t}" : "=r"(done) : "r"(mb), "r"(par) : "memory");
    if (!done) {
        asm volatile("{\n\t.reg .pred P1;\n\tWL_%=:\n\t"
            "mbarrier.try_wait.parity.acquire.cluster.shared::cta.b64 P1, [%0], %1, 0x989680;\n\t"
            "@P1 bra.uni WD_%=;\n\tbra.uni WL_%=;\n\tWD_%=:\n\t}"
            :: "r"(mb), "r"(par) : "memory");
    }
    ph++;
}

// ---------------- h0 ----------------
__global__ void k_h0(const float* __restrict__ initial, const float* __restrict__ in_w,
                     const float* __restrict__ in_b, float* __restrict__ out, int write_feat) {
    int b = blockIdx.x, t = threadIdx.x;
    __shared__ float si[DIN];
    if (t < DIN) si[t] = initial[b * DIN + t];
    __syncthreads();
    float acc = in_b[t];
    #pragma unroll 8
    for (int k = 0; k < DIN; ++k) acc = fmaf(si[k], in_w[k * HH + t], acc);
    g_h0[b * HH + t] = acc;
    if (write_feat) out[(size_t)b * (SS + 1) * HH + t] = acc;
}

// ---------------- fp16 operand conversion ----------------
__global__ void k_splitA(const float* __restrict__ logsig) {
    int i = blockIdx.x, c = threadIdx.x;
    float v = (c < DD) ? logsig[(size_t)i * (DD + 1) + 1 + c] : 0.f;
    g_A2[(size_t)i * KT + c] = __float2half_rn(v);
}
__global__ void k_splitB(const float* __restrict__ ml_w) {
    int j = blockIdx.x, c = threadIdx.x;
    int w = j >> 7, h = j & 127;
    float v = (c < DD) ? ml_w[(size_t)w * (HH * DD) + h * DD + c] : 0.f;
    g_B2[(size_t)j * KT + c] = __float2half_rn(v);
}

// ---------------- cbias ----------------
__global__ void k_cbias(const float* __restrict__ logsig, const float* __restrict__ ml_b) {
    extern __shared__ float s[];
    float* mlb  = s;
    float* coef = s + HH * 137;
    float* part = coef + 160;
    int t = threadIdx.x;
    for (int idx = t; idx < HH * DD; idx += 256) {
        int h = idx / DD, d = idx - h * DD;
        mlb[h * 137 + d] = ml_b[idx];
    }
    int i0 = blockIdx.x * 16;
    for (int r = 0; r < 16; ++r) {
        int i = i0 + r;
        __syncthreads();
        if (t < DD) coef[t] = logsig[(size_t)i * (DD + 1) + 1 + t];
        __syncthreads();
        int h = t & 127, half = t >> 7;
        int d0 = half * 68;
        float acc = 0.f;
        #pragma unroll 4
        for (int d = 0; d < 68; ++d) acc = fmaf(coef[d0 + d], mlb[h * 137 + d0 + d], acc);
        part[t] = acc;
        __syncthreads();
        if (t < HH) g_cbias[(size_t)i * HH + t] = part[t] + part[t + 128];
    }
}

// ---------------- single-pass fp16 GEMM (K=144) -> fp16 G ----------------
#define SRK  56
#define ABUF (128 * SRK)
#define SMEM_G2 (4 * ABUF * 2)        // 57344 B

__device__ __forceinline__ void ldm_x4(uint32_t* r, uint32_t addr) {
    asm volatile("ldmatrix.sync.aligned.m8n8.x4.shared.b16 {%0,%1,%2,%3}, [%4];"
                 : "=r"(r[0]), "=r"(r[1]), "=r"(r[2]), "=r"(r[3]) : "r"(addr));
}
__device__ __forceinline__ void mma_f16(float* c, const uint32_t* a, const uint32_t* b) {
    asm volatile(
        "mma.sync.aligned.m16n8k16.row.col.f32.f16.f16.f32 "
        "{%0,%1,%2,%3}, {%4,%5,%6,%7}, {%8,%9}, {%0,%1,%2,%3};"
        : "+f"(c[0]), "+f"(c[1]), "+f"(c[2]), "+f"(c[3])
        : "r"(a[0]), "r"(a[1]), "r"(a[2]), "r"(a[3]), "r"(b[0]), "r"(b[1]));
}

__device__ __forceinline__ void load_chunk(int i0, int j0, int ch,
                                           uint32_t smA, uint32_t smB, int t) {
    const __half* Ab = g_A2 + (size_t)i0 * KT + ch * KC;
    const __half* Bb = g_B2 + (size_t)j0 * KT + ch * KC;
    #pragma unroll
    for (int rep = 0; rep < 6; ++rep) {
        int id = rep * 256 + t;
        int isB = (id >= 768);
        int lid = isB ? id - 768 : id;
        int row = lid / 6, c16 = lid - row * 6;
        const __half* g = (isB ? Bb : Ab) + (size_t)row * KT + c16 * 8;
        uint32_t s = (isB ? smB : smA) + (uint32_t)(row * SRK + c16 * 8) * 2;
        cp16(s, g);
    }
}

__global__ void __launch_bounds__(256, 2) k_gemm_mma() {
    extern __shared__ __half sm[];
    uint32_t smBase = s2u(sm);
    uint32_t smA[2] = { smBase, smBase + 2u * ABUF * 2u };
    uint32_t smB[2] = { smBase + (uint32_t)ABUF * 2u, smBase + 3u * ABUF * 2u };

    int t = threadIdx.x, lane = t & 31;
    int wid = t >> 5, wm = wid >> 2, wn = wid & 3;
    int j0 = blockIdx.x << 7, i0 = blockIdx.y << 7;

    int arow = (lane & 7) + ((lane >> 3) & 1) * 8;
    int acol = (lane >> 4) * 8;
    int brow = (lane & 7) + ((lane >> 4) & 1) * 8;
    int bcol = ((lane >> 3) & 1) * 8;
    uint32_t aoff[4], boff[2];
    #pragma unroll
    for (int mf = 0; mf < 4; ++mf)
        aoff[mf] = (uint32_t)((wm * 64 + mf * 16 + arow) * SRK + acol) * 2;
    #pragma unroll
    for (int nf = 0; nf < 2; ++nf)
        boff[nf] = (uint32_t)((wn * 32 + nf * 16 + brow) * SRK + bcol) * 2;

    load_chunk(i0, j0, 0, smA[0], smB[0], t); cp_commit();
    load_chunk(i0, j0, 1, smA[1], smB[1], t); cp_commit();

    float acc[4][4][4];
    #pragma unroll
    for (int i = 0; i < 4; ++i)
        #pragma unroll
        for (int j = 0; j < 4; ++j)
            #pragma unroll
            for (int q = 0; q < 4; ++q) acc[i][j][q] = 0.f;

    #pragma unroll
    for (int ch = 0; ch < NCH; ++ch) {
        if (ch == 0) cp_wait<1>();
        else if (ch == 1) cp_wait<1>();
        else cp_wait<0>();
        __syncthreads();
        uint32_t bA = smA[ch % 2], bB = smB[ch % 2];
        #pragma unroll
        for (int kg = 0; kg < 3; ++kg) {
            uint32_t koff = (uint32_t)kg * 32;
            uint32_t aR[4][4], bR[4][2];
            #pragma unroll
            for (int mf = 0; mf < 4; ++mf) ldm_x4(aR[mf], bA + aoff[mf] + koff);
            #pragma unroll
            for (int nf = 0; nf < 2; ++nf) {
                uint32_t r4[4];
                ldm_x4(r4, bB + boff[nf] + koff);
                bR[nf * 2][0] = r4[0]; bR[nf * 2][1] = r4[1];
                bR[nf * 2 + 1][0] = r4[2]; bR[nf * 2 + 1][1] = r4[3];
            }
            #pragma unroll
            for (int mf = 0; mf < 4; ++mf)
                #pragma unroll
                for (int nf = 0; nf < 4; ++nf)
                    mma_f16(acc[mf][nf], aR[mf], bR[nf]);
        }
        if (ch == 0) {
            __syncthreads();
            load_chunk(i0, j0, 2, smA[0], smB[0], t);
            cp_commit();
        }
    }

    int rbase = i0 + wm * 64 + (lane >> 2);
    int cbase = j0 + wn * 32 + (lane & 3) * 2;
    #pragma unroll
    for (int mf = 0; mf < 4; ++mf) {
        #pragma unroll
        for (int nf = 0; nf < 4; ++nf) {
            size_t r0 = (size_t)(rbase + mf * 16) * GN + cbase + nf * 8;
            size_t r1 = r0 + 8 * (size_t)GN;
            *(__half2*)&g_Gh[r0] = __floats2half2_rn(acc[mf][nf][0], acc[mf][nf][1]);
            *(__half2*)&g_Gh[r1] = __floats2half2_rn(acc[mf][nf][2], acc[mf][nf][3]);
        }
    }
}

// ---------------- cluster-4 scan: reg-weights + mbarrier stage sync ----------------
#define OFF_W1  0        // 8192 floats
#define OFF_B1  8192
#define OFF_B2  8256
#define OFF_BV  8320
#define OFF_SY  8384     // 512
#define OFF_SYM 8896
#define OFF_SK1 9408
#define OFF_SK2 9920
#define OFF_A   10432    // 1024
#define OFF_B2F 11456    // 1024
#define OFF_RED 12480    // 2048
#define OFF_MB  14528    // 8B mbarrier
#define SCAN_FLOATS 14536
#define SCAN_SMEM (SCAN_FLOATS * 4)

// stage1: K=128, weights from smem
__device__ __forceinline__ void mlp_stage_sm(const float* __restrict__ sIn,
                                             const float* __restrict__ W,
                                             const float* __restrict__ bias,
                                             float* sRed, uint32_t outAddr,
                                             int r, int t, uint32_t mb, int& ph) {
    int kc = t >> 6, n = t & 63;
    float2 a01 = make_float2(0.f, 0.f), a23 = make_float2(0.f, 0.f);
    const float* Wp = W + n;
    #pragma unroll 8
    for (int kk = 0; kk < 32; ++kk) {
        int k = kc * 32 + kk;
        float w = Wp[k * 64];
        float4 a = *(const float4*)&sIn[k * 4];
        float2 w2 = make_float2(w, w);
        a01 = fma2(a01, make_float2(a.x, a.y), w2);
        a23 = fma2(a23, make_float2(a.z, a.w), w2);
    }
    *(float4*)&sRed[t * 4] = make_float4(a01.x, a01.y, a23.x, a23.y);
    __syncthreads();
    {
        int n2 = t & 63, j = t >> 6;
        float v = sRed[(0 * 64 + n2) * 4 + j] + sRed[(1 * 64 + n2) * 4 + j]
                + sRed[(2 * 64 + n2) * 4 + j] + sRed[(3 * 64 + n2) * 4 + j];
        v += bias[n2];
        v = fmaxf(v, 0.f);
        uint32_t addr = outAddr + (uint32_t)(((64 * r + n2) << 2) + j) * 4u;
        #pragma unroll
        for (int p = 0; p < CL; ++p) st_cluster_f32(addr, (uint32_t)p, v);
    }
    stage_bar(mb, ph, t);
}

// K=256 stages, weights in registers (64 per thread)
template <int ACT>
__device__ __forceinline__ void mlp_stage_reg(const float* __restrict__ sIn,
                                              const float (&wreg)[64],
                                              const float* __restrict__ bias,
                                              float* sRed, uint32_t outAddr,
                                              int r, int t, uint32_t mb, int& ph) {
    int kc = t >> 6;
    float2 a01 = make_float2(0.f, 0.f), a23 = make_float2(0.f, 0.f);
    #pragma unroll
    for (int kk = 0; kk < 64; ++kk) {
        int k = kc * 64 + kk;
        float4 a = *(const float4*)&sIn[k * 4];
        float w = wreg[kk];
        float2 w2 = make_float2(w, w);
        a01 = fma2(a01, make_float2(a.x, a.y), w2);
        a23 = fma2(a23, make_float2(a.z, a.w), w2);
    }
    *(float4*)&sRed[t * 4] = make_float4(a01.x, a01.y, a23.x, a23.y);
    __syncthreads();
    {
        int n2 = t & 63, j = t >> 6;
        float v = sRed[(0 * 64 + n2) * 4 + j] + sRed[(1 * 64 + n2) * 4 + j]
                + sRed[(2 * 64 + n2) * 4 + j] + sRed[(3 * 64 + n2) * 4 + j];
        v += bias[n2];
        if (ACT == 0) v = fmaxf(v, 0.f); else v = tanhf(v);
        uint32_t addr = outAddr + (uint32_t)(((64 * r + n2) << 2) + j) * 4u;
        #pragma unroll
        for (int p = 0; p < CL; ++p) st_cluster_f32(addr, (uint32_t)p, v);
    }
    stage_bar(mb, ph, t);
}

__device__ __forceinline__ void contract_stage(const float* __restrict__ sV,
                                               int m, int b0, int r,
                                               float* sRed, uint32_t kAddr,
                                               const float* __restrict__ cbias,
                                               int t, uint32_t mb, int& ph) {
    int wg = t >> 4, hp = t & 15;
    float cb = 0.f;
    if (t < 128) {
        int j = t & 3, hh = t >> 2;
        cb = cbias[((size_t)(b0 + j) * SS + m) * HH + 32 * r + hh];
    }
    const __half2* Gp[RPC];
    #pragma unroll
    for (int j = 0; j < RPC; ++j)
        Gp[j] = (const __half2*)(g_Gh + ((size_t)(b0 + j) * SS + m) * GN) + 16 * r + hp;
    float2 acc[RPC];
    #pragma unroll
    for (int j = 0; j < RPC; ++j) acc[j] = make_float2(0.f, 0.f);
    #pragma unroll 4
    for (int ww = 0; ww < 16; ++ww) {
        int w = wg * 16 + ww;
        float4 v4 = *(const float4*)&sV[w * 4];
        const float* vp = (const float*)&v4;
        #pragma unroll
        for (int j = 0; j < RPC; ++j) {
            float2 g = __half22float2(Gp[j][(size_t)w * 64]);
            acc[j] = fma2(acc[j], make_float2(vp[j], vp[j]), g);
        }
    }
    #pragma unroll
    for (int j = 0; j < RPC; ++j) {
        sRed[wg * 128 + (2 * hp) * 4 + j]     = acc[j].x;
        sRed[wg * 128 + (2 * hp + 1) * 4 + j] = acc[j].y;
    }
    __syncthreads();
    if (t < 128) {
        int j = t & 3, hh = t >> 2;
        float v = cb;
        #pragma unroll
        for (int q = 0; q < 16; ++q) v += sRed[q * 128 + hh * 4 + j];
        uint32_t addr = kAddr + (uint32_t)(((32 * r + hh) << 2) + j) * 4u;
        #pragma unroll
        for (int p = 0; p < CL; ++p) st_cluster_f32(addr, (uint32_t)p, v);
    }
    stage_bar(mb, ph, t);
}

__global__ void __launch_bounds__(256, 1) __cluster_dims__(CL, 1, 1)
k_scan(const float* __restrict__ h1_w, const float* __restrict__ h1_b,
       const float* __restrict__ h2_w, const float* __restrict__ h2_b,
       const float* __restrict__ vo_w, const float* __restrict__ vo_b,
       float* __restrict__ out, int write_feat, long long last_off) {
    extern __shared__ float ss[];
    float* w1s = ss + OFF_W1;
    float* b1s = ss + OFF_B1;
    float* b2s = ss + OFF_B2;
    float* bvs = ss + OFF_BV;
    float* sy  = ss + OFF_SY;
    float* sym = ss + OFF_SYM;
    float* sk1 = ss + OFF_SK1;
    float* sk2 = ss + OFF_SK2;
    float* sbA = ss + OFF_A;
    float* sbB = ss + OFF_B2F;
    float* sRed = ss + OFF_RED;

    int t = threadIdx.x;
    int r = (int)cl_rank();
    int b0 = (blockIdx.x >> 2) * RPC;

    uint32_t aA  = s2u(sbA), aB = s2u(sbB);
    uint32_t aK1 = s2u(sk1), aK2 = s2u(sk2);
    uint32_t mb  = s2u(ss + OFF_MB);

    // register-resident weights for the two K=256 stages
    float wreg2[64], wregV[64];
    {
        int kc = t >> 6, n = t & 63;
        #pragma unroll
        for (int kk = 0; kk < 64; ++kk) {
            wreg2[kk] = h2_w[(kc * 64 + kk) * WWID + 64 * r + n];
            wregV[kk] = vo_w[(kc * 64 + kk) * WWID + 64 * r + n];
        }
    }
    for (int idx = t; idx < HH * 64; idx += 256) {
        int k = idx >> 6, n = idx & 63;
        w1s[idx] = h1_w[k * WWID + 64 * r + n];
    }
    if (t < 64) {
        b1s[t] = h1_b[64 * r + t];
        b2s[t] = h2_b[64 * r + t];
        bvs[t] = vo_b[64 * r + t];
    }
    for (int idx = t; idx < HH * RPC; idx += 256) {
        int h = idx >> 2, j = idx & 3;
        sy[idx] = g_h0[(b0 + j) * HH + h];
    }
    if (t == 0) MBAR_INIT(mb, CL);
    __syncthreads();
    CL_SYNC();   // barriers initialized cluster-wide before first remote arrive

    int ph = 0;
    for (int n = 0; n < SS; ++n) {
        int m1 = (n > 0) ? (n - 1) : 0;
        mlp_stage_sm(sy, w1s, b1s, sRed, aA, r, t, mb, ph);
        mlp_stage_reg<0>(sbA, wreg2, b2s, sRed, aB, r, t, mb, ph);
        mlp_stage_reg<1>(sbB, wregV, bvs, sRed, aA, r, t, mb, ph);
        contract_stage(sbA, m1, b0, r, sRed, aK1, g_cbias, t, mb, ph);
        {
            int i0 = t, i1 = t + 256;
            sym[i0] = sy[i0] + sk1[i0];
            sym[i1] = sy[i1] + sk1[i1];
        }
        __syncthreads();
        mlp_stage_sm(sym, w1s, b1s, sRed, aA, r, t, mb, ph);
        mlp_stage_reg<0>(sbA, wreg2, b2s, sRed, aB, r, t, mb, ph);
        mlp_stage_reg<1>(sbB, wregV, bvs, sRed, aA, r, t, mb, ph);
        contract_stage(sbA, n, b0, r, sRed, aK2, g_cbias, t, mb, ph);
        {
            #pragma unroll
            for (int u = 0; u < 2; ++u) {
                int v = t + u * 256;
                int h = v >> 2, j = v & 3;
                float yn = sy[v] + 0.5f * (sk1[v] + sk2[v]);
                sy[v] = yn;
                if (write_feat)
                    out[(size_t)(b0 + j) * (SS + 1) * HH + (size_t)(n + 1) * HH + h] = yn;
                if (n == SS - 1 && last_off >= 0)
                    out[(size_t)last_off + (size_t)(b0 + j) * HH + h] = yn;
            }
        }
        __syncthreads();
    }
}

// ---------------- launch ----------------
extern "C" void kernel_launch(void* const* d_in, const int* in_sizes, int n_in,
                              void* d_out, int out_size) {
    const float* logsig  = (const float*)d_in[1];
    const float* initial = (const float*)d_in[2];
    const float* in_w    = (const float*)d_in[3];
    const float* in_b    = (const float*)d_in[4];
    const float* h1_w    = (const float*)d_in[5];
    const float* h1_b    = (const float*)d_in[6];
    const float* h2_w    = (const float*)d_in[7];
    const float* h2_b    = (const float*)d_in[8];
    const float* vo_w    = (const float*)d_in[9];
    const float* vo_b    = (const float*)d_in[10];
    const float* ml_w    = (const float*)d_in[11];
    const float* ml_b    = (const float*)d_in[12];
    float* out = (float*)d_out;

    const long long feat_sz = (long long)BB * (SS + 1) * HH;
    const long long last_sz = (long long)BB * HH;
    int write_feat = (out_size >= feat_sz) ? 1 : 0;
    long long last_off = -1;
    if (out_size >= feat_sz + last_sz) last_off = feat_sz;
    else if (!write_feat && out_size >= last_sz) last_off = 0;

    const int cbias_smem = (HH * 137 + 160 + 256) * 4;
    cudaFuncSetAttribute(k_cbias,    cudaFuncAttributeMaxDynamicSharedMemorySize, cbias_smem);
    cudaFuncSetAttribute(k_gemm_mma, cudaFuncAttributeMaxDynamicSharedMemorySize, SMEM_G2);
    cudaFuncSetAttribute(k_scan,     cudaFuncAttributeMaxDynamicSharedMemorySize, SCAN_SMEM);

    k_h0<<<BB, HH>>>(initial, in_w, in_b, out, write_feat);
    k_splitA<<<GM, KT>>>(logsig);
    k_splitB<<<GN, KT>>>(ml_w);
    k_gemm_mma<<<dim3(GN / 128, GM / 128), 256, SMEM_G2>>>();
    k_cbias<<<GM / 16, 256, cbias_smem>>>(logsig, ml_b);
    k_scan<<<SCAN_CTAS, 256, SCAN_SMEM>>>(h1_w, h1_b, h2_w, h2_b, vo_w, vo_b,
                                          out, write_feat, last_off);
}